// round 2
// baseline (speedup 1.0000x reference)
#include <cuda_runtime.h>
#include <cstdint>
#include <math_constants.h>

// Problem constants
#define BB 64
#define SS 4096
#define DD 1024
#define SPLITS 16
#define CHUNK (SS / SPLITS)   // 256 rows per CTA
#define TILE 16               // rows per smem tile (== warps per CTA)
#define THREADS 512
#define NPART (BB * SPLITS)

// Scratch (device globals — no allocation allowed)
__device__ float g_ctx[NPART * DD];
__device__ float g_m[NPART];
__device__ float g_l[NPART];

__device__ __forceinline__ void cp_async16(void* smem_ptr, const void* gptr) {
    uint32_t s = (uint32_t)__cvta_generic_to_shared(smem_ptr);
    asm volatile("cp.async.cg.shared.global [%0], [%1], 16;\n" :: "r"(s), "l"(gptr));
}
__device__ __forceinline__ void cp_commit() {
    asm volatile("cp.async.commit_group;\n" ::: "memory");
}
__device__ __forceinline__ void cp_wait1() {
    asm volatile("cp.async.wait_group 1;\n" ::: "memory");
}

// Kernel 1: per-(batch, split) partial online-softmax attention pooling.
// Tile pipeline: 2 x (16 rows x 4KB) smem buffers, cp.async double buffered.
__global__ __launch_bounds__(THREADS, 1)
void attn_partial_kernel(const float* __restrict__ inp,
                         const int*   __restrict__ lens,
                         const float* __restrict__ w) {
    extern __shared__ float smem[];                 // 2 * TILE * DD floats
    __shared__ float sc[TILE];                      // raw scores of tile rows
    __shared__ float pp[TILE];                      // exp(score - m_new)
    __shared__ float s_alpha;                       // rescale factor

    const int sp  = blockIdx.x;
    const int b   = blockIdx.y;
    const int idx = b * SPLITS + sp;
    const int tid = threadIdx.x;
    const int lane = tid & 31;
    const int wid  = tid >> 5;

    const int len = lens[b];
    const int s0  = sp * CHUNK;
    const int s1  = min(s0 + CHUNK, len);

    if (s1 <= s0) {
        // Empty partial: write neutral element.
        for (int d = tid; d < DD; d += THREADS) g_ctx[idx * DD + d] = 0.0f;
        if (tid == 0) { g_m[idx] = -CUDART_INF_F; g_l[idx] = 0.0f; }
        return;
    }

    // Weight vector in registers: lane pattern matches the score-phase LDS.128 pattern.
    const float4* w4 = (const float4*)w;
    float4 wr[8];
#pragma unroll
    for (int j = 0; j < 8; j++) wr[j] = w4[lane + 32 * j];

    float* buf0 = smem;
    float* buf1 = smem + TILE * DD;

    const int nrows_total = s1 - s0;
    const int ntiles = (nrows_total + TILE - 1) / TILE;

    // Prologue: load tile 0
    {
        const int nr = min(TILE, nrows_total);
        const int n4 = nr * (DD / 4);
        const float4* src = (const float4*)(inp + ((size_t)b * SS + s0) * DD);
        float4* dst = (float4*)buf0;
        for (int i = tid; i < n4; i += THREADS) cp_async16(dst + i, src + i);
        cp_commit();
    }

    float m_run = -CUDART_INF_F;   // maintained by warp 0 only (uniform in-warp)
    float l_run = 0.0f;            // maintained by warp 0 only
    float cx = 0.0f, cy = 0.0f;    // ctx: thread owns columns 2*tid, 2*tid+1

    for (int t = 0; t < ntiles; t++) {
        // Issue next tile load
        if (t + 1 < ntiles) {
            const int row0 = s0 + (t + 1) * TILE;
            const int nr = min(TILE, s1 - row0);
            const int n4 = nr * (DD / 4);
            const float4* src = (const float4*)(inp + ((size_t)b * SS + row0) * DD);
            float4* dst = (float4*)((t + 1) & 1 ? buf1 : buf0);
            for (int i = tid; i < n4; i += THREADS) cp_async16(dst + i, src + i);
        }
        cp_commit();
        cp_wait1();            // current tile's group complete
        __syncthreads();

        const int nrows = min(TILE, s1 - (s0 + t * TILE));
        float* buf = (t & 1) ? buf1 : buf0;

        // --- Score phase: warp `wid` dots row `wid` against w ---
        if (wid < nrows) {
            const float4* row4 = (const float4*)(buf + wid * DD);
            float acc = 0.0f;
#pragma unroll
            for (int j = 0; j < 8; j++) {
                float4 v = row4[lane + 32 * j];
                acc += v.x * wr[j].x + v.y * wr[j].y + v.z * wr[j].z + v.w * wr[j].w;
            }
#pragma unroll
            for (int off = 16; off > 0; off >>= 1)
                acc += __shfl_xor_sync(0xFFFFFFFFu, acc, off);
            if (lane == 0) sc[wid] = acc;
        }
        __syncthreads();

        // --- Online softmax bookkeeping: warp 0 only ---
        if (wid == 0) {
            float s = (lane < nrows) ? sc[lane] : -CUDART_INF_F;
            float mt = s;
#pragma unroll
            for (int off = 16; off > 0; off >>= 1)
                mt = fmaxf(mt, __shfl_xor_sync(0xFFFFFFFFu, mt, off));
            const float m_new = fmaxf(m_run, mt);
            const float alpha = __expf(m_run - m_new);
            float p = (lane < nrows) ? __expf(s - m_new) : 0.0f;
            float psum = p;
#pragma unroll
            for (int off = 16; off > 0; off >>= 1)
                psum += __shfl_xor_sync(0xFFFFFFFFu, psum, off);
            l_run = l_run * alpha + psum;
            m_run = m_new;
            if (lane < TILE) pp[lane] = p;
            if (lane == 0) s_alpha = alpha;
        }
        __syncthreads();

        // --- Accumulate phase: each thread owns a float2 column pair ---
        const float alpha = s_alpha;
        cx *= alpha; cy *= alpha;
        const float2* buf2 = (const float2*)buf;
#pragma unroll 4
        for (int r = 0; r < nrows; r++) {
            const float p = pp[r];
            const float2 v = buf2[r * (DD / 2) + tid];
            cx += p * v.x;
            cy += p * v.y;
        }
        __syncthreads();   // buffer reuse guard
    }

    // Write partial
    float2* out2 = (float2*)(g_ctx + (size_t)idx * DD);
    out2[tid] = make_float2(cx, cy);
    if (tid == 0) { g_m[idx] = m_run; g_l[idx] = l_run; }
}

// Kernel 2: merge SPLITS partials per batch (standard split-softmax merge).
__global__ __launch_bounds__(256)
void attn_reduce_kernel(float* __restrict__ out) {
    __shared__ float mm[SPLITS], ll[SPLITS];
    const int b = blockIdx.x;
    const int tid = threadIdx.x;

    if (tid < SPLITS) {
        mm[tid] = g_m[b * SPLITS + tid];
        ll[tid] = g_l[b * SPLITS + tid];
    }
    __syncthreads();

    float M = -CUDART_INF_F;
#pragma unroll
    for (int i = 0; i < SPLITS; i++) M = fmaxf(M, mm[i]);

    float wg[SPLITS];
    float L = 0.0f;
#pragma unroll
    for (int i = 0; i < SPLITS; i++) {
        wg[i] = __expf(mm[i] - M);
        L += ll[i] * wg[i];
    }
    const float invL = 1.0f / L;

    // Thread owns float4 at columns 4*tid .. 4*tid+3
    float4 acc = make_float4(0.f, 0.f, 0.f, 0.f);
#pragma unroll
    for (int i = 0; i < SPLITS; i++) {
        const float4 v = ((const float4*)(g_ctx + (size_t)(b * SPLITS + i) * DD))[tid];
        acc.x += wg[i] * v.x;
        acc.y += wg[i] * v.y;
        acc.z += wg[i] * v.z;
        acc.w += wg[i] * v.w;
    }
    acc.x *= invL; acc.y *= invL; acc.z *= invL; acc.w *= invL;
    ((float4*)(out + (size_t)b * DD))[tid] = acc;
}

extern "C" void kernel_launch(void* const* d_in, const int* in_sizes, int n_in,
                              void* d_out, int out_size) {
    const float* inp  = (const float*)d_in[0];
    const int*   lens = (const int*)d_in[1];
    const float* w    = (const float*)d_in[2];
    // d_in[3] = bias: softmax is shift-invariant -> ignored.
    float* out = (float*)d_out;

    const int smem_bytes = 2 * TILE * DD * sizeof(float);   // 128 KB
    cudaFuncSetAttribute(attn_partial_kernel,
                         cudaFuncAttributeMaxDynamicSharedMemorySize, smem_bytes);

    dim3 grid1(SPLITS, BB);
    attn_partial_kernel<<<grid1, THREADS, smem_bytes>>>(inp, lens, w);
    attn_reduce_kernel<<<BB, 256>>>(out);
}

// round 4
// speedup vs baseline: 1.1089x; 1.1089x over previous
#include <cuda_runtime.h>
#include <cstdint>
#include <math_constants.h>

// Problem constants
#define BB 64
#define SS 4096
#define DD 1024
#define SPLITS 32
#define CHUNK (SS / SPLITS)   // 128 rows per CTA
#define TILE 8                // rows per smem tile (== warps per CTA)
#define THREADS 256
#define NPART (BB * SPLITS)

// Scratch (device globals — no allocation allowed)
__device__ float g_ctx[NPART * DD];
__device__ float g_m[NPART];
__device__ float g_l[NPART];

__device__ __forceinline__ void cp_async16(void* smem_ptr, const void* gptr) {
    uint32_t s = (uint32_t)__cvta_generic_to_shared(smem_ptr);
    asm volatile("cp.async.cg.shared.global [%0], [%1], 16;\n" :: "r"(s), "l"(gptr));
}
__device__ __forceinline__ void cp_commit() {
    asm volatile("cp.async.commit_group;\n" ::: "memory");
}
__device__ __forceinline__ void cp_wait1() {
    asm volatile("cp.async.wait_group 1;\n" ::: "memory");
}

// Kernel 1: per-(batch, split) partial online-softmax attention pooling.
// Tile pipeline: 2 x (8 rows x 4KB) smem buffers, cp.async double buffered.
// 64KB dynamic smem -> 3 CTAs/SM.
__global__ __launch_bounds__(THREADS, 3)
void attn_partial_kernel(const float* __restrict__ inp,
                         const int*   __restrict__ lens,
                         const float* __restrict__ w) {
    extern __shared__ float smem[];                 // 2 * TILE * DD floats = 64KB
    __shared__ float sc[TILE];                      // raw scores of tile rows
    __shared__ float pp[TILE];                      // exp(score - m_new)
    __shared__ float s_alpha;                       // rescale factor

    const int sp  = blockIdx.x;
    const int b   = blockIdx.y;
    const int idx = b * SPLITS + sp;
    const int tid = threadIdx.x;
    const int lane = tid & 31;
    const int wid  = tid >> 5;

    const int len = lens[b];
    const int s0  = sp * CHUNK;
    const int s1  = min(s0 + CHUNK, len);

    if (s1 <= s0) {
        // Empty partial: write neutral element.
        float4 z = make_float4(0.f, 0.f, 0.f, 0.f);
        ((float4*)(g_ctx + (size_t)idx * DD))[tid] = z;
        if (tid == 0) { g_m[idx] = -CUDART_INF_F; g_l[idx] = 0.0f; }
        return;
    }

    // Weight vector in registers: lane pattern matches the score-phase LDS.128 pattern.
    const float4* w4 = (const float4*)w;
    float4 wr[8];
#pragma unroll
    for (int j = 0; j < 8; j++) wr[j] = w4[lane + 32 * j];

    float* buf0 = smem;
    float* buf1 = smem + TILE * DD;

    const int nrows_total = s1 - s0;
    const int ntiles = (nrows_total + TILE - 1) / TILE;

    // Prologue: load tile 0
    {
        const int nr = min(TILE, nrows_total);
        const int n4 = nr * (DD / 4);
        const float4* src = (const float4*)(inp + ((size_t)b * SS + s0) * DD);
        float4* dst = (float4*)buf0;
        for (int i = tid; i < n4; i += THREADS) cp_async16(dst + i, src + i);
        cp_commit();
    }

    float m_run = -CUDART_INF_F;   // maintained by warp 0 only (uniform in-warp)
    float l_run = 0.0f;            // maintained by warp 0 only
    // ctx: thread owns columns 4*tid .. 4*tid+3
    float c0 = 0.f, c1 = 0.f, c2 = 0.f, c3 = 0.f;

    for (int t = 0; t < ntiles; t++) {
        // Issue next tile load
        if (t + 1 < ntiles) {
            const int row0 = s0 + (t + 1) * TILE;
            const int nr = min(TILE, s1 - row0);
            const int n4 = nr * (DD / 4);
            const float4* src = (const float4*)(inp + ((size_t)b * SS + row0) * DD);
            float4* dst = (float4*)((t + 1) & 1 ? buf1 : buf0);
            for (int i = tid; i < n4; i += THREADS) cp_async16(dst + i, src + i);
        }
        cp_commit();
        cp_wait1();            // current tile's group complete
        __syncthreads();

        const int nrows = min(TILE, s1 - (s0 + t * TILE));
        float* buf = (t & 1) ? buf1 : buf0;

        // --- Score phase: warp `wid` dots row `wid` against w (8 warps, 8 rows) ---
        if (wid < nrows) {
            const float4* row4 = (const float4*)(buf + wid * DD);
            float acc = 0.0f;
#pragma unroll
            for (int j = 0; j < 8; j++) {
                float4 v = row4[lane + 32 * j];
                acc += v.x * wr[j].x + v.y * wr[j].y + v.z * wr[j].z + v.w * wr[j].w;
            }
#pragma unroll
            for (int off = 16; off > 0; off >>= 1)
                acc += __shfl_xor_sync(0xFFFFFFFFu, acc, off);
            if (lane == 0) sc[wid] = acc;
        }
        __syncthreads();

        // --- Online softmax bookkeeping: warp 0 only ---
        if (wid == 0) {
            float s = (lane < nrows) ? sc[lane] : -CUDART_INF_F;
            float mt = s;
#pragma unroll
            for (int off = 16; off > 0; off >>= 1)
                mt = fmaxf(mt, __shfl_xor_sync(0xFFFFFFFFu, mt, off));
            const float m_new = fmaxf(m_run, mt);
            const float alpha = __expf(m_run - m_new);
            float p = (lane < nrows) ? __expf(s - m_new) : 0.0f;
            float psum = p;
#pragma unroll
            for (int off = 16; off > 0; off >>= 1)
                psum += __shfl_xor_sync(0xFFFFFFFFu, psum, off);
            l_run = l_run * alpha + psum;
            m_run = m_new;
            if (lane < TILE) pp[lane] = p;
            if (lane == 0) s_alpha = alpha;
        }
        __syncthreads();

        // --- Accumulate phase: each thread owns a float4 column group ---
        const float alpha = s_alpha;
        c0 *= alpha; c1 *= alpha; c2 *= alpha; c3 *= alpha;
        const float4* buf4 = (const float4*)buf;
#pragma unroll
        for (int r = 0; r < TILE; r++) {
            if (r >= nrows) break;
            const float p = pp[r];
            const float4 v = buf4[r * (DD / 4) + tid];
            c0 += p * v.x;
            c1 += p * v.y;
            c2 += p * v.z;
            c3 += p * v.w;
        }
        __syncthreads();   // buffer reuse guard
    }

    // Write partial
    ((float4*)(g_ctx + (size_t)idx * DD))[tid] = make_float4(c0, c1, c2, c3);
    if (tid == 0) { g_m[idx] = m_run; g_l[idx] = l_run; }
}

// Kernel 2: merge SPLITS partials per batch (standard split-softmax merge).
// grid (BB, 2): each block handles 512 columns of one batch.
__global__ __launch_bounds__(128)
void attn_reduce_kernel(float* __restrict__ out) {
    __shared__ float mm[SPLITS], ll[SPLITS];
    const int b = blockIdx.x;
    const int half = blockIdx.y;          // 0 or 1
    const int tid = threadIdx.x;          // 0..127

    if (tid < SPLITS) {
        mm[tid] = g_m[b * SPLITS + tid];
        ll[tid] = g_l[b * SPLITS + tid];
    }
    __syncthreads();

    float M = -CUDART_INF_F;
#pragma unroll
    for (int i = 0; i < SPLITS; i++) M = fmaxf(M, mm[i]);

    float L = 0.0f;
    float wg[SPLITS];
#pragma unroll
    for (int i = 0; i < SPLITS; i++) {
        wg[i] = __expf(mm[i] - M);
        L += ll[i] * wg[i];
    }
    const float invL = 1.0f / L;

    // This block's float4 column index within the batch row
    const int c4 = half * 128 + tid;      // 0..255

    float4 acc = make_float4(0.f, 0.f, 0.f, 0.f);
#pragma unroll
    for (int i = 0; i < SPLITS; i++) {
        const float4 v = ((const float4*)(g_ctx + (size_t)(b * SPLITS + i) * DD))[c4];
        acc.x += wg[i] * v.x;
        acc.y += wg[i] * v.y;
        acc.z += wg[i] * v.z;
        acc.w += wg[i] * v.w;
    }
    acc.x *= invL; acc.y *= invL; acc.z *= invL; acc.w *= invL;
    ((float4*)(out + (size_t)b * DD))[c4] = acc;
}

extern "C" void kernel_launch(void* const* d_in, const int* in_sizes, int n_in,
                              void* d_out, int out_size) {
    const float* inp  = (const float*)d_in[0];
    const int*   lens = (const int*)d_in[1];
    const float* w    = (const float*)d_in[2];
    // d_in[3] = bias: softmax is shift-invariant -> ignored.
    float* out = (float*)d_out;

    const int smem_bytes = 2 * TILE * DD * sizeof(float);   // 64 KB
    cudaFuncSetAttribute(attn_partial_kernel,
                         cudaFuncAttributeMaxDynamicSharedMemorySize, smem_bytes);

    dim3 grid1(SPLITS, BB);
    attn_partial_kernel<<<grid1, THREADS, smem_bytes>>>(inp, lens, w);
    dim3 grid2(BB, 2);
    attn_reduce_kernel<<<grid2, 128>>>(out);
}

// round 6
// speedup vs baseline: 1.3842x; 1.2482x over previous
#include <cuda_runtime.h>
#include <cstdint>
#include <math_constants.h>

// Problem constants
#define BB 64
#define SS 4096
#define DD 1024
#define SPLITS 32
#define CHUNK (SS / SPLITS)   // 128 rows per CTA
#define TILE 8                // rows per smem tile (== warps per CTA)
#define THREADS 256
#define NPART (BB * SPLITS)
#define ROW_BYTES (DD * 4)    // 4 KB
#define TILE_BYTES (TILE * ROW_BYTES)  // 32 KB

// Scratch (device globals — no allocation allowed)
__device__ float g_ctx[NPART * DD];
__device__ float g_m[NPART];
__device__ float g_l[NPART];

__device__ __forceinline__ uint32_t smem_u32(const void* p) {
    return (uint32_t)__cvta_generic_to_shared(p);
}

__device__ __forceinline__ void mbar_init(uint32_t mbar, uint32_t count) {
    asm volatile("mbarrier.init.shared.b64 [%0], %1;" :: "r"(mbar), "r"(count) : "memory");
}
__device__ __forceinline__ void mbar_expect_tx(uint32_t mbar, uint32_t bytes) {
    asm volatile("mbarrier.arrive.expect_tx.shared.b64 _, [%0], %1;"
                 :: "r"(mbar), "r"(bytes) : "memory");
}
__device__ __forceinline__ void mbar_wait(uint32_t mbar, uint32_t parity) {
    asm volatile(
        "{\n\t"
        ".reg .pred P;\n\t"
        "WAIT_%=: \n\t"
        "mbarrier.try_wait.parity.shared.b64 P, [%0], %1;\n\t"
        "@!P bra WAIT_%=;\n\t"
        "}"
        :: "r"(mbar), "r"(parity) : "memory");
}
// 1D bulk TMA: gmem -> smem, completion via mbarrier complete_tx
__device__ __forceinline__ void tma_bulk_g2s(uint32_t dst_smem, const void* src,
                                             uint32_t bytes, uint32_t mbar) {
    asm volatile(
        "cp.async.bulk.shared::cluster.global.mbarrier::complete_tx::bytes "
        "[%0], [%1], %2, [%3];"
        :: "r"(dst_smem), "l"(src), "r"(bytes), "r"(mbar) : "memory");
}

// Kernel 1: per-(batch, split) partial online-softmax attention pooling.
// Tile pipeline: 2 x (8 rows x 4KB) smem buffers, TMA bulk double buffered.
// 64KB dynamic smem -> 3 CTAs/SM.
__global__ __launch_bounds__(THREADS, 3)
void attn_partial_kernel(const float* __restrict__ inp,
                         const int*   __restrict__ lens,
                         const float* __restrict__ w) {
    extern __shared__ float smem[];                 // 2 * TILE * DD floats = 64KB
    __shared__ float sc[TILE];                      // raw scores of tile rows
    __shared__ float pp[TILE];                      // exp(score - m_new)
    __shared__ float s_alpha;                       // rescale factor
    __shared__ __align__(8) uint64_t mbar_store[2]; // one mbarrier per stage

    const int sp  = blockIdx.x;
    const int b   = blockIdx.y;
    const int idx = b * SPLITS + sp;
    const int tid = threadIdx.x;
    const int lane = tid & 31;
    const int wid  = tid >> 5;

    const int len = lens[b];
    const int s0  = sp * CHUNK;
    const int s1  = min(s0 + CHUNK, len);

    if (s1 <= s0) {
        // Empty partial: write neutral element.
        ((float4*)(g_ctx + (size_t)idx * DD))[tid] = make_float4(0.f, 0.f, 0.f, 0.f);
        if (tid == 0) { g_m[idx] = -CUDART_INF_F; g_l[idx] = 0.0f; }
        return;
    }

    const uint32_t mbar0 = smem_u32(&mbar_store[0]);
    const uint32_t mbar1 = smem_u32(&mbar_store[1]);
    if (tid == 0) {
        mbar_init(mbar0, 1);
        mbar_init(mbar1, 1);
    }
    __syncthreads();

    // Weight vector in registers: lane pattern matches the score-phase LDS.128 pattern.
    const float4* w4 = (const float4*)w;
    float4 wr[8];
#pragma unroll
    for (int j = 0; j < 8; j++) wr[j] = w4[lane + 32 * j];

    float* buf0 = smem;
    float* buf1 = smem + TILE * DD;
    const uint32_t sbuf0 = smem_u32(buf0);
    const uint32_t sbuf1 = smem_u32(buf1);

    const int nrows_total = s1 - s0;
    const int ntiles = (nrows_total + TILE - 1) / TILE;

    // Prologue: issue tile 0 (stage 0)
    if (tid == 0) {
        const int nr = min(TILE, nrows_total);
        const uint32_t bytes = nr * ROW_BYTES;
        mbar_expect_tx(mbar0, bytes);
        tma_bulk_g2s(sbuf0, inp + ((size_t)b * SS + s0) * DD, bytes, mbar0);
    }

    float m_run = -CUDART_INF_F;   // maintained by warp 0 only (uniform in-warp)
    float l_run = 0.0f;            // maintained by warp 0 only
    // ctx: thread owns columns 4*tid .. 4*tid+3
    float c0 = 0.f, c1 = 0.f, c2 = 0.f, c3 = 0.f;

    for (int t = 0; t < ntiles; t++) {
        // Issue next tile load into the other stage
        if (t + 1 < ntiles && tid == 0) {
            const int row0 = s0 + (t + 1) * TILE;
            const int nr = min(TILE, s1 - row0);
            const uint32_t bytes = nr * ROW_BYTES;
            const uint32_t mb = ((t + 1) & 1) ? mbar1 : mbar0;
            const uint32_t db = ((t + 1) & 1) ? sbuf1 : sbuf0;
            mbar_expect_tx(mb, bytes);
            tma_bulk_g2s(db, inp + ((size_t)b * SS + row0) * DD, bytes, mb);
        }

        // Wait for current tile
        const uint32_t mb_cur = (t & 1) ? mbar1 : mbar0;
        mbar_wait(mb_cur, (t >> 1) & 1);
        __syncthreads();

        const int nrows = min(TILE, s1 - (s0 + t * TILE));
        float* buf = (t & 1) ? buf1 : buf0;

        // --- Score phase: warp `wid` dots row `wid` against w (8 warps, 8 rows) ---
        if (wid < nrows) {
            const float4* row4 = (const float4*)(buf + wid * DD);
            float acc = 0.0f;
#pragma unroll
            for (int j = 0; j < 8; j++) {
                float4 v = row4[lane + 32 * j];
                acc += v.x * wr[j].x + v.y * wr[j].y + v.z * wr[j].z + v.w * wr[j].w;
            }
#pragma unroll
            for (int off = 16; off > 0; off >>= 1)
                acc += __shfl_xor_sync(0xFFFFFFFFu, acc, off);
            if (lane == 0) sc[wid] = acc;
        }
        __syncthreads();

        // --- Online softmax bookkeeping: warp 0 only ---
        if (wid == 0) {
            float s = (lane < nrows) ? sc[lane] : -CUDART_INF_F;
            float mt = s;
#pragma unroll
            for (int off = 16; off > 0; off >>= 1)
                mt = fmaxf(mt, __shfl_xor_sync(0xFFFFFFFFu, mt, off));
            const float m_new = fmaxf(m_run, mt);
            const float alpha = __expf(m_run - m_new);
            float p = (lane < nrows) ? __expf(s - m_new) : 0.0f;
            float psum = p;
#pragma unroll
            for (int off = 16; off > 0; off >>= 1)
                psum += __shfl_xor_sync(0xFFFFFFFFu, psum, off);
            l_run = l_run * alpha + psum;
            m_run = m_new;
            if (lane < TILE) pp[lane] = p;
            if (lane == 0) s_alpha = alpha;
        }
        __syncthreads();

        // --- Accumulate phase: each thread owns a float4 column group ---
        const float alpha = s_alpha;
        c0 *= alpha; c1 *= alpha; c2 *= alpha; c3 *= alpha;
        const float4* buf4 = (const float4*)buf;
#pragma unroll
        for (int r = 0; r < TILE; r++) {
            if (r >= nrows) break;
            const float p = pp[r];
            const float4 v = buf4[r * (DD / 4) + tid];
            c0 += p * v.x;
            c1 += p * v.y;
            c2 += p * v.z;
            c3 += p * v.w;
        }
        __syncthreads();   // buffer reuse guard (before next TMA overwrites)
    }

    // Write partial
    ((float4*)(g_ctx + (size_t)idx * DD))[tid] = make_float4(c0, c1, c2, c3);
    if (tid == 0) { g_m[idx] = m_run; g_l[idx] = l_run; }
}

// Kernel 2: merge SPLITS partials per batch (split-softmax merge).
// grid (BB, 2): each block handles 512 columns of one batch.
// 256 threads: two groups of 128, each sums 16 splits, merged in smem.
__global__ __launch_bounds__(256)
void attn_reduce_kernel(float* __restrict__ out) {
    __shared__ float mm[SPLITS], ll[SPLITS];
    __shared__ float4 acc_sh[128];
    const int b = blockIdx.x;
    const int half = blockIdx.y;          // 0 or 1
    const int tid = threadIdx.x;          // 0..255
    const int col = tid & 127;            // float4 column within this half
    const int grp = tid >> 7;             // 0 or 1: split-half

    if (tid < SPLITS) {
        mm[tid] = g_m[b * SPLITS + tid];
        ll[tid] = g_l[b * SPLITS + tid];
    }
    __syncthreads();

    float M = -CUDART_INF_F;
#pragma unroll
    for (int i = 0; i < SPLITS; i++) M = fmaxf(M, mm[i]);

    float L = 0.0f;
    float wg[SPLITS];
#pragma unroll
    for (int i = 0; i < SPLITS; i++) {
        wg[i] = __expf(mm[i] - M);
        L += ll[i] * wg[i];
    }
    const float invL = 1.0f / L;

    const int c4 = half * 128 + col;      // 0..255 float4 index within batch row

    float4 acc = make_float4(0.f, 0.f, 0.f, 0.f);
#pragma unroll
    for (int k = 0; k < SPLITS / 2; k++) {
        const int i = grp * (SPLITS / 2) + k;
        const float4 v = ((const float4*)(g_ctx + (size_t)(b * SPLITS + i) * DD))[c4];
        acc.x += wg[i] * v.x;
        acc.y += wg[i] * v.y;
        acc.z += wg[i] * v.z;
        acc.w += wg[i] * v.w;
    }

    if (grp == 1) acc_sh[col] = acc;
    __syncthreads();
    if (grp == 0) {
        const float4 o = acc_sh[col];
        acc.x = (acc.x + o.x) * invL;
        acc.y = (acc.y + o.y) * invL;
        acc.z = (acc.z + o.z) * invL;
        acc.w = (acc.w + o.w) * invL;
        ((float4*)(out + (size_t)b * DD))[c4] = acc;
    }
}

extern "C" void kernel_launch(void* const* d_in, const int* in_sizes, int n_in,
                              void* d_out, int out_size) {
    const float* inp  = (const float*)d_in[0];
    const int*   lens = (const int*)d_in[1];
    const float* w    = (const float*)d_in[2];
    // d_in[3] = bias: softmax is shift-invariant -> ignored.
    float* out = (float*)d_out;

    const int smem_bytes = 2 * TILE * DD * sizeof(float);   // 64 KB
    cudaFuncSetAttribute(attn_partial_kernel,
                         cudaFuncAttributeMaxDynamicSharedMemorySize, smem_bytes);

    dim3 grid1(SPLITS, BB);
    attn_partial_kernel<<<grid1, THREADS, smem_bytes>>>(inp, lens, w);
    dim3 grid2(BB, 2);
    attn_reduce_kernel<<<grid2, 256>>>(out);
}